// round 2
// baseline (speedup 1.0000x reference)
#include <cuda_runtime.h>
#include <math.h>

#define NB   32
#define C    256
#define CI   64
#define L    6
#define T    64
#define V    50
#define K    3
#define EPSV 1e-5f

#define XT_ELEMS  (NB*C*L*V)      // 2,457,600
#define Y_ELEMS   (NB*CI*L*V)     // 614,400
#define OUT_ELEMS (NB*C*T*V)      // 26,214,400

__device__ __align__(16) float g_xt[XT_ELEMS];
__device__ __align__(16) float g_WdT[C*CI];     // [c][d]
__device__ float g_y[Y_ELEMS];
__device__ float g_stat1[2*CI];
__device__ float g_epre[NB*CI*L*K];
__device__ float g_stat2[2*CI];
__device__ float g_att[NB*C*L];

__constant__ int c_off[7] = {0, 6, 20, 42, 62, 78, 94};
__constant__ int c_layers[94] = {
    1, 0, 20, 26, 25, 45,
    0, 20, 12, 16, 2, 4, 8, 25, 45, 37, 41, 27, 29, 33,
    12, 16, 2, 4, 8, 13, 17, 3, 5, 9, 3, 28, 37, 41, 27, 29, 33, 38, 42, 28, 30, 34,
    13, 17, 3, 5, 9, 14, 18, 6, 10, 3, 28, 38, 42, 28, 30, 34, 39, 43, 31, 35,
    14, 18, 6, 10, 15, 19, 7, 11, 39, 43, 31, 35, 40, 44, 32, 36,
    15, 19, 7, 11, 21, 22, 23, 24, 40, 44, 32, 36, 46, 47, 48, 49
};

// ---------------------------------------------------------------------------
// K1: x_t = max over T, float2-vectorized. Also transposes W_down (blocks 0-63).
// ---------------------------------------------------------------------------
__global__ void __launch_bounds__(256) k_maxT(const float* __restrict__ x,
                                              const float* __restrict__ Wd) {
    if (blockIdx.x < 64) {
        // g_WdT[c][d] = Wd[d][c]
        g_WdT[threadIdx.x * CI + blockIdx.x] = Wd[blockIdx.x * C + threadIdx.x];
    }
    int i2 = blockIdx.x * 256 + threadIdx.x;           // over XT_ELEMS/2
    if (i2 >= XT_ELEMS / 2) return;
    int v2  = i2 % (V / 2);
    int ncl = i2 / (V / 2);
    const float2* p = (const float2*)x + (size_t)ncl * (T * V / 2) + v2;
    float ax0 = -INFINITY, ay0 = -INFINITY, ax1 = -INFINITY, ay1 = -INFINITY;
    float ax2 = -INFINITY, ay2 = -INFINITY, ax3 = -INFINITY, ay3 = -INFINITY;
#pragma unroll
    for (int t = 0; t < T; t += 4) {
        float2 q0 = __ldg(p + (t + 0) * (V / 2));
        float2 q1 = __ldg(p + (t + 1) * (V / 2));
        float2 q2 = __ldg(p + (t + 2) * (V / 2));
        float2 q3 = __ldg(p + (t + 3) * (V / 2));
        ax0 = fmaxf(ax0, q0.x); ay0 = fmaxf(ay0, q0.y);
        ax1 = fmaxf(ax1, q1.x); ay1 = fmaxf(ay1, q1.y);
        ax2 = fmaxf(ax2, q2.x); ay2 = fmaxf(ay2, q2.y);
        ax3 = fmaxf(ax3, q3.x); ay3 = fmaxf(ay3, q3.y);
    }
    float2 r;
    r.x = fmaxf(fmaxf(ax0, ax1), fmaxf(ax2, ax3));
    r.y = fmaxf(fmaxf(ay0, ay1), fmaxf(ay2, ay3));
    ((float2*)g_xt)[i2] = r;
}

// ---------------------------------------------------------------------------
// K2: y[n,d,l,v] = sum_c WdT[c][d] * xt[n,c,l,v] + b_down[d]
// Block per (n,l), 256 threads (200 active): v=tid%50, dg=tid/50, 16 d each.
// ---------------------------------------------------------------------------
__global__ void __launch_bounds__(256) k_down(const float* __restrict__ bd) {
    int n = blockIdx.x / L;
    int l = blockIdx.x % L;
    __shared__ float sx[128 * V];   // 25.6 KB
    int tid = threadIdx.x;
    int v = tid % V;
    int dg = tid / V;               // 0..3 active
    float acc[16];
#pragma unroll
    for (int i = 0; i < 16; i++) acc[i] = 0.f;

    for (int chunk = 0; chunk < 2; chunk++) {
        int cbase = chunk * 128;
        for (int j = tid; j < 128 * V; j += 256) {
            int cc = j / V, vv = j % V;
            sx[j] = g_xt[(n * C + cbase + cc) * (L * V) + l * V + vv];
        }
        __syncthreads();
        if (tid < 200) {
#pragma unroll 4
            for (int cc = 0; cc < 128; cc++) {
                float xv = sx[cc * V + v];
                const float4* w4 = (const float4*)(g_WdT + (cbase + cc) * CI + dg * 16);
                float4 w0 = __ldg(w4 + 0);
                float4 w1 = __ldg(w4 + 1);
                float4 w2 = __ldg(w4 + 2);
                float4 w3 = __ldg(w4 + 3);
                acc[0]  += w0.x * xv; acc[1]  += w0.y * xv; acc[2]  += w0.z * xv; acc[3]  += w0.w * xv;
                acc[4]  += w1.x * xv; acc[5]  += w1.y * xv; acc[6]  += w1.z * xv; acc[7]  += w1.w * xv;
                acc[8]  += w2.x * xv; acc[9]  += w2.y * xv; acc[10] += w2.z * xv; acc[11] += w2.w * xv;
                acc[12] += w3.x * xv; acc[13] += w3.y * xv; acc[14] += w3.z * xv; acc[15] += w3.w * xv;
            }
        }
        __syncthreads();
    }
    if (tid < 200) {
#pragma unroll
        for (int i = 0; i < 16; i++) {
            int d = dg * 16 + i;
            g_y[((n * CI + d) * L + l) * V + v] = acc[i] + __ldg(&bd[d]);
        }
    }
}

// ---------------------------------------------------------------------------
// K3: BN1 stats per channel d over (n,l,v): 9600 elems. Block per d.
// ---------------------------------------------------------------------------
__global__ void __launch_bounds__(256) k_bn1() {
    int d = blockIdx.x;
    __shared__ float s1[256], s2[256];
    float sum = 0.f, sq = 0.f;
    for (int i = threadIdx.x; i < NB * L * V; i += 256) {
        int n = i / (L * V), r = i % (L * V);
        float yv = g_y[n * (CI * L * V) + d * (L * V) + r];
        sum += yv; sq += yv * yv;
    }
    s1[threadIdx.x] = sum; s2[threadIdx.x] = sq;
    __syncthreads();
    for (int st = 128; st > 0; st >>= 1) {
        if (threadIdx.x < st) { s1[threadIdx.x] += s1[threadIdx.x + st];
                                s2[threadIdx.x] += s2[threadIdx.x + st]; }
        __syncthreads();
    }
    if (threadIdx.x == 0) {
        float cnt = (float)(NB * L * V);
        float mean = s1[0] / cnt;
        float var  = s2[0] / cnt - mean * mean;
        g_stat1[d]      = mean;
        g_stat1[CI + d] = rsqrtf(var + EPSV);
    }
}

// ---------------------------------------------------------------------------
// K4: fused xs + graph + edge GEMM. Block per n, 384 threads = (l*64 + d).
// ---------------------------------------------------------------------------
__global__ void __launch_bounds__(384) k_graph(const float* __restrict__ g1,
                                               const float* __restrict__ b1,
                                               const float* __restrict__ We) {
    int n = blockIdx.x;
    int tid = threadIdx.x;
    int d = tid % CI;
    int l = tid / CI;               // 0..5
    __shared__ float sWe[CI * 129];   // padded: sWe[d*129 + c], c in [0,128)
    __shared__ float sxs[CI * L];     // [c][l]
    __shared__ float sinn[L * L];
    __shared__ int   sidx[L * K];

    for (int j = tid; j < CI * 2 * CI; j += 384) {
        int dd = j >> 7, cc = j & 127;
        sWe[dd * 129 + cc] = We[j];
    }

    // xs[d][l]
    {
        float mean = g_stat1[d], rstd = g_stat1[CI + d];
        float gm = __ldg(&g1[d]), bt = __ldg(&b1[d]);
        int base = (n * CI + d) * (L * V) + l * V;
        int o0 = c_off[l], o1 = c_off[l + 1];
        float s = 0.f;
        for (int j = o0; j < o1; j++) {
            float yv = (g_y[base + c_layers[j]] - mean) * rstd * gm + bt;
            s += fmaxf(yv, 0.f);
        }
        sxs[d * L + l] = s / (float)(o1 - o0);
    }
    __syncthreads();

    // inner[l][m]
    if (tid < L * L) {
        int ll = tid / L, mm = tid % L;
        float s = 0.f;
        for (int c = 0; c < CI; c++) s += sxs[c * L + ll] * sxs[c * L + mm];
        sinn[tid] = s;
    }
    __syncthreads();
    // top-k over pd[l][m] = 2*inner - inner[l][l] - inner[m][m]
    if (tid < L) {
        int taken = 0;
        float xl = sinn[tid * L + tid];
        for (int k = 0; k < K; k++) {
            int best = -1; float bv = -INFINITY;
            for (int m = 0; m < L; m++) {
                if ((taken >> m) & 1) continue;
                float pv = 2.f * sinn[tid * L + m] - xl - sinn[m * L + m];
                if (pv > bv) { bv = pv; best = m; }
            }
            taken |= (1 << best);
            sidx[tid * K + k] = best;
        }
    }
    __syncthreads();

    // e_pre[n,d,l,k]: thread (d,l) computes K accumulators over 64 c
    int i0 = sidx[l * K + 0], i1 = sidx[l * K + 1], i2 = sidx[l * K + 2];
    float a0 = 0.f, a1 = 0.f, a2 = 0.f;
#pragma unroll 4
    for (int c = 0; c < CI; c++) {
        float wa = sWe[d * 129 + c];
        float wb = sWe[d * 129 + CI + c];
        float ctr = sxs[c * L + l];
        float base = (wb - wa) * ctr;
        a0 += wa * sxs[c * L + i0] + base;
        a1 += wa * sxs[c * L + i1] + base;
        a2 += wa * sxs[c * L + i2] + base;
    }
    int ob = ((n * CI + d) * L + l) * K;
    g_epre[ob + 0] = a0;
    g_epre[ob + 1] = a1;
    g_epre[ob + 2] = a2;
}

// ---------------------------------------------------------------------------
// K5: BN2 stats per channel over (n,l,k): 576 elems. Block per d, 64 thr.
// ---------------------------------------------------------------------------
__global__ void __launch_bounds__(64) k_bn2() {
    int d = blockIdx.x;
    __shared__ float s1[64], s2[64];
    float sum = 0.f, sq = 0.f;
    for (int i = threadIdx.x; i < NB * L * K; i += 64) {
        int n = i / (L * K), r = i % (L * K);
        float e = g_epre[n * (CI * L * K) + d * (L * K) + r];
        sum += e; sq += e * e;
    }
    s1[threadIdx.x] = sum; s2[threadIdx.x] = sq;
    __syncthreads();
    for (int st = 32; st > 0; st >>= 1) {
        if (threadIdx.x < st) { s1[threadIdx.x] += s1[threadIdx.x + st];
                                s2[threadIdx.x] += s2[threadIdx.x + st]; }
        __syncthreads();
    }
    if (threadIdx.x == 0) {
        float cnt = (float)(NB * L * K);
        float mean = s1[0] / cnt;
        float var  = s2[0] / cnt - mean * mean;
        g_stat2[d]      = mean;
        g_stat2[CI + d] = rsqrtf(var + EPSV);
    }
}

// ---------------------------------------------------------------------------
// K6: e = max_k lrelu(bn2(e_pre)); att = sigmoid(W_agg @ e + b_agg). Block/n.
// ---------------------------------------------------------------------------
__global__ void __launch_bounds__(256) k_att(const float* __restrict__ g2,
                                             const float* __restrict__ b2,
                                             const float* __restrict__ Wa,
                                             const float* __restrict__ ba) {
    int n = blockIdx.x;
    int tid = threadIdx.x;
    __shared__ float se[CI * L];      // [d][l]
    if (tid < CI) {
        int d = tid;
        float mean = g_stat2[d], rstd = g_stat2[CI + d];
        float gm = __ldg(&g2[d]), bt = __ldg(&b2[d]);
#pragma unroll
        for (int l = 0; l < L; l++) {
            float mx = -INFINITY;
#pragma unroll
            for (int k = 0; k < K; k++) {
                float e = (g_epre[((n * CI + d) * L + l) * K + k] - mean) * rstd * gm + bt;
                e = (e >= 0.f) ? e : 0.2f * e;
                mx = fmaxf(mx, e);
            }
            se[d * L + l] = mx;
        }
    }
    __syncthreads();
    float acc[L];
#pragma unroll
    for (int l = 0; l < L; l++) acc[l] = 0.f;
    for (int d = 0; d < CI; d++) {
        float w = __ldg(&Wa[tid * CI + d]);
#pragma unroll
        for (int l = 0; l < L; l++) acc[l] += w * se[d * L + l];
    }
    float bb = __ldg(&ba[tid]);
#pragma unroll
    for (int l = 0; l < L; l++) {
        float a = acc[l] + bb;
        g_att[(n * C + tid) * L + l] = 1.f / (1.f + expf(-a));
    }
}

// ---------------------------------------------------------------------------
// K7: out[n,c,t,v] = sum_l x[n,c,l,t,v]*att[n,c,l], float4-vectorized.
// ---------------------------------------------------------------------------
__global__ void __launch_bounds__(256) k_out(const float* __restrict__ x,
                                             float* __restrict__ out) {
    int i4 = blockIdx.x * 256 + threadIdx.x;           // over OUT_ELEMS/4
    if (i4 >= OUT_ELEMS / 4) return;
    int tv4 = i4 % (T * V / 4);                        // 0..799
    int nc  = i4 / (T * V / 4);
    const float4* px = (const float4*)x + (size_t)nc * (L * T * V / 4) + tv4;
    float a0 = __ldg(&g_att[nc * L + 0]);
    float a1 = __ldg(&g_att[nc * L + 1]);
    float a2 = __ldg(&g_att[nc * L + 2]);
    float a3 = __ldg(&g_att[nc * L + 3]);
    float a4 = __ldg(&g_att[nc * L + 4]);
    float a5 = __ldg(&g_att[nc * L + 5]);
    float4 x0 = __ldg(px + 0 * 800);
    float4 x1 = __ldg(px + 1 * 800);
    float4 x2 = __ldg(px + 2 * 800);
    float4 x3 = __ldg(px + 3 * 800);
    float4 x4 = __ldg(px + 4 * 800);
    float4 x5 = __ldg(px + 5 * 800);
    float4 r;
    r.x = a0*x0.x + a1*x1.x + a2*x2.x + a3*x3.x + a4*x4.x + a5*x5.x;
    r.y = a0*x0.y + a1*x1.y + a2*x2.y + a3*x3.y + a4*x4.y + a5*x5.y;
    r.z = a0*x0.z + a1*x1.z + a2*x2.z + a3*x3.z + a4*x4.z + a5*x5.z;
    r.w = a0*x0.w + a1*x1.w + a2*x2.w + a3*x3.w + a4*x4.w + a5*x5.w;
    ((float4*)out)[i4] = r;
}

// ---------------------------------------------------------------------------
extern "C" void kernel_launch(void* const* d_in, const int* in_sizes, int n_in,
                              void* d_out, int out_size) {
    const float* x      = (const float*)d_in[0];
    const float* W_down = (const float*)d_in[1];
    const float* b_down = (const float*)d_in[2];
    const float* gamma1 = (const float*)d_in[3];
    const float* beta1  = (const float*)d_in[4];
    const float* W_edge = (const float*)d_in[5];
    const float* gamma2 = (const float*)d_in[6];
    const float* beta2  = (const float*)d_in[7];
    const float* W_agg  = (const float*)d_in[8];
    const float* b_agg  = (const float*)d_in[9];
    float* out = (float*)d_out;

    k_maxT<<<(XT_ELEMS / 2 + 255) / 256, 256>>>(x, W_down);
    k_down<<<NB * L, 256>>>(b_down);
    k_bn1<<<CI, 256>>>();
    k_graph<<<NB, 384>>>(gamma1, beta1, W_edge);
    k_bn2<<<CI, 64>>>();
    k_att<<<NB, 256>>>(gamma2, beta2, W_agg, b_agg);
    k_out<<<(OUT_ELEMS / 4 + 255) / 256, 256>>>(x, out);
}

// round 3
// speedup vs baseline: 1.3040x; 1.3040x over previous
#include <cuda_runtime.h>
#include <math.h>

#define NB   32
#define C    256
#define CI   64
#define L    6
#define T    64
#define V    50
#define K    3
#define EPSV 1e-5f

#define XT_ELEMS  (NB*C*L*V)      // 2,457,600
#define Y_ELEMS   (NB*CI*L*V)     // 614,400
#define OUT_ELEMS (NB*C*T*V)      // 26,214,400

__device__ __align__(16) float g_xt[XT_ELEMS];
__device__ __align__(16) float g_WdT[C*CI];     // [c][d]
__device__ __align__(16) float g_y[Y_ELEMS];
__device__ float g_epre[NB*CI*L*K];
__device__ float g_att[NB*C*L];
__device__ float g_s1[CI], g_q1[CI];            // BN1 running sums
__device__ float g_s2[CI], g_q2[CI];            // BN2 running sums

__constant__ int c_off[7] = {0, 6, 20, 42, 62, 78, 94};
__constant__ int c_layers[94] = {
    1, 0, 20, 26, 25, 45,
    0, 20, 12, 16, 2, 4, 8, 25, 45, 37, 41, 27, 29, 33,
    12, 16, 2, 4, 8, 13, 17, 3, 5, 9, 3, 28, 37, 41, 27, 29, 33, 38, 42, 28, 30, 34,
    13, 17, 3, 5, 9, 14, 18, 6, 10, 3, 28, 38, 42, 28, 30, 34, 39, 43, 31, 35,
    14, 18, 6, 10, 15, 19, 7, 11, 39, 43, 31, 35, 40, 44, 32, 36,
    15, 19, 7, 11, 21, 22, 23, 24, 40, 44, 32, 36, 46, 47, 48, 49
};

// ---------------------------------------------------------------------------
// K1: x_t = max over T (float2). Side jobs: transpose W_down, zero BN sums.
// ---------------------------------------------------------------------------
__global__ void __launch_bounds__(256) k_maxT(const float* __restrict__ x,
                                              const float* __restrict__ Wd) {
    if (blockIdx.x < 64) {
        g_WdT[threadIdx.x * CI + blockIdx.x] = Wd[blockIdx.x * C + threadIdx.x];
    } else if (blockIdx.x == 64 && threadIdx.x < CI) {
        int t = threadIdx.x;
        g_s1[t] = 0.f; g_q1[t] = 0.f; g_s2[t] = 0.f; g_q2[t] = 0.f;
    }
    int i2 = blockIdx.x * 256 + threadIdx.x;           // over XT_ELEMS/2
    if (i2 >= XT_ELEMS / 2) return;
    int v2  = i2 % (V / 2);
    int ncl = i2 / (V / 2);
    const float2* p = (const float2*)x + (size_t)ncl * (T * V / 2) + v2;
    float ax0 = -INFINITY, ay0 = -INFINITY, ax1 = -INFINITY, ay1 = -INFINITY;
    float ax2 = -INFINITY, ay2 = -INFINITY, ax3 = -INFINITY, ay3 = -INFINITY;
#pragma unroll
    for (int t = 0; t < T; t += 4) {
        float2 q0 = __ldg(p + (t + 0) * (V / 2));
        float2 q1 = __ldg(p + (t + 1) * (V / 2));
        float2 q2 = __ldg(p + (t + 2) * (V / 2));
        float2 q3 = __ldg(p + (t + 3) * (V / 2));
        ax0 = fmaxf(ax0, q0.x); ay0 = fmaxf(ay0, q0.y);
        ax1 = fmaxf(ax1, q1.x); ay1 = fmaxf(ay1, q1.y);
        ax2 = fmaxf(ax2, q2.x); ay2 = fmaxf(ay2, q2.y);
        ax3 = fmaxf(ax3, q3.x); ay3 = fmaxf(ay3, q3.y);
    }
    float2 r;
    r.x = fmaxf(fmaxf(ax0, ax1), fmaxf(ax2, ax3));
    r.y = fmaxf(fmaxf(ay0, ay1), fmaxf(ay2, ay3));
    ((float2*)g_xt)[i2] = r;
}

// ---------------------------------------------------------------------------
// K2: y = W_down @ xt + b (smem-tiled), fused BN1 partial sums.
// Block per (n,l), 256 threads (200 active): v=tid%50, dg=tid/50.
// ---------------------------------------------------------------------------
__global__ void __launch_bounds__(256) k_down(const float* __restrict__ bd) {
    int n = blockIdx.x / L;
    int l = blockIdx.x % L;
    __shared__ __align__(16) float sW[64 * 64];   // [c_local][d]  16KB
    __shared__ __align__(16) float sx[64 * V];    // [c_local][v]  12.8KB
    int tid = threadIdx.x;
    int v = tid % V;
    int dg = tid / V;               // 0..3 active (tid<200)
    float acc[16];
#pragma unroll
    for (int i = 0; i < 16; i++) acc[i] = 0.f;

    for (int ch = 0; ch < 4; ch++) {
        int cb = ch * 64;
        // W chunk: 1024 float4 (d-contiguous)
        const float4* Wg = (const float4*)(g_WdT + cb * CI);
        float4* sW4 = (float4*)sW;
        for (int j = tid; j < 1024; j += 256) sW4[j] = __ldg(Wg + j);
        // xt chunk: 1600 float2
        for (int j = tid; j < 1600; j += 256) {
            int cl = j / 25, v2 = j % 25;
            ((float2*)sx)[cl * 25 + v2] =
                *(const float2*)(g_xt + (size_t)(n * C + cb + cl) * (L * V) + l * V + v2 * 2);
        }
        __syncthreads();
        if (tid < 200) {
#pragma unroll 4
            for (int cl = 0; cl < 64; cl++) {
                float xv = sx[cl * V + v];
                const float4* w4 = (const float4*)(sW + cl * 64 + dg * 16);
                float4 w0 = w4[0], w1 = w4[1], w2 = w4[2], w3 = w4[3];
                acc[0]  += w0.x * xv; acc[1]  += w0.y * xv; acc[2]  += w0.z * xv; acc[3]  += w0.w * xv;
                acc[4]  += w1.x * xv; acc[5]  += w1.y * xv; acc[6]  += w1.z * xv; acc[7]  += w1.w * xv;
                acc[8]  += w2.x * xv; acc[9]  += w2.y * xv; acc[10] += w2.z * xv; acc[11] += w2.w * xv;
                acc[12] += w3.x * xv; acc[13] += w3.y * xv; acc[14] += w3.z * xv; acc[15] += w3.w * xv;
            }
        }
        __syncthreads();
    }
    // Epilogue: bias, store y, stage for BN1 block-reduce (reuse sx: 64d x 50v)
    if (tid < 200) {
#pragma unroll
        for (int i = 0; i < 16; i++) {
            int d = dg * 16 + i;
            float yv = acc[i] + __ldg(&bd[d]);
            g_y[((n * CI + d) * L + l) * V + v] = yv;
            sx[d * V + v] = yv;
        }
    }
    __syncthreads();
    if (tid < CI) {
        float s = 0.f, q = 0.f;
#pragma unroll
        for (int vv = 0; vv < V; vv++) {
            float yv = sx[tid * V + vv];
            s += yv; q += yv * yv;
        }
        atomicAdd(&g_s1[tid], s);
        atomicAdd(&g_q1[tid], q);
    }
}

// ---------------------------------------------------------------------------
// K3: fused BN1-finalize + xs + topk graph + edge GEMM + BN2 partial sums.
// Block per n, 384 threads = (l*64 + d).
// ---------------------------------------------------------------------------
__global__ void __launch_bounds__(384) k_graph(const float* __restrict__ g1,
                                               const float* __restrict__ b1,
                                               const float* __restrict__ We) {
    int n = blockIdx.x;
    int tid = threadIdx.x;
    int d = tid & 63;
    int l = tid / 64;               // 0..5
    __shared__ float sWe[CI * 129];   // padded: conflict-free, 33KB
    __shared__ float sxs[CI * L];     // [c][l]
    __shared__ float sstat[2 * CI];
    __shared__ float sinn[L * L];
    __shared__ int   sidx[L * K];
    __shared__ float sred[L * CI], sredq[L * CI];

    // W_edge -> smem via float4
    const float4* We4 = (const float4*)We;
    for (int j = tid; j < 2048; j += 384) {
        float4 w = __ldg(We4 + j);
        int dd = j >> 5, c4 = (j & 31) * 4;
        float* p = &sWe[dd * 129 + c4];
        p[0] = w.x; p[1] = w.y; p[2] = w.z; p[3] = w.w;
    }
    // BN1 finalize
    if (tid < CI) {
        float s = g_s1[tid], q = g_q1[tid];
        float cnt = (float)(NB * L * V);
        float mean = s / cnt;
        float var  = q / cnt - mean * mean;
        sstat[tid]      = mean;
        sstat[CI + tid] = rsqrtf(var + EPSV);
    }
    __syncthreads();

    // xs[d][l]
    {
        float mean = sstat[d], rstd = sstat[CI + d];
        float gm = __ldg(&g1[d]), bt = __ldg(&b1[d]);
        int base = (n * CI + d) * (L * V) + l * V;
        int o0 = c_off[l], o1 = c_off[l + 1];
        float s = 0.f;
        for (int j = o0; j < o1; j++) {
            float yv = (__ldg(&g_y[base + c_layers[j]]) - mean) * rstd * gm + bt;
            s += fmaxf(yv, 0.f);
        }
        sxs[d * L + l] = s / (float)(o1 - o0);
    }
    __syncthreads();

    if (tid < L * L) {
        int ll = tid / L, mm = tid % L;
        float s = 0.f;
        for (int c = 0; c < CI; c++) s += sxs[c * L + ll] * sxs[c * L + mm];
        sinn[tid] = s;
    }
    __syncthreads();
    if (tid < L) {
        int taken = 0;
        float xl = sinn[tid * L + tid];
        for (int k = 0; k < K; k++) {
            int best = -1; float bv = -INFINITY;
            for (int m = 0; m < L; m++) {
                if ((taken >> m) & 1) continue;
                float pv = 2.f * sinn[tid * L + m] - xl - sinn[m * L + m];
                if (pv > bv) { bv = pv; best = m; }
            }
            taken |= (1 << best);
            sidx[tid * K + k] = best;
        }
    }
    __syncthreads();

    // e_pre[n,d,l,k]
    int i0 = sidx[l * K + 0], i1 = sidx[l * K + 1], i2 = sidx[l * K + 2];
    float a0 = 0.f, a1 = 0.f, a2 = 0.f;
#pragma unroll 4
    for (int c = 0; c < CI; c++) {
        float wa = sWe[d * 129 + c];
        float wb = sWe[d * 129 + CI + c];
        float ctr = sxs[c * L + l];
        float base = (wb - wa) * ctr;
        a0 += wa * sxs[c * L + i0] + base;
        a1 += wa * sxs[c * L + i1] + base;
        a2 += wa * sxs[c * L + i2] + base;
    }
    int ob = ((n * CI + d) * L + l) * K;
    g_epre[ob + 0] = a0;
    g_epre[ob + 1] = a1;
    g_epre[ob + 2] = a2;
    sred [l * CI + d] = a0 + a1 + a2;
    sredq[l * CI + d] = a0 * a0 + a1 * a1 + a2 * a2;
    __syncthreads();
    if (tid < CI) {
        float s = 0.f, q = 0.f;
#pragma unroll
        for (int ll = 0; ll < L; ll++) {
            s += sred [ll * CI + tid];
            q += sredq[ll * CI + tid];
        }
        atomicAdd(&g_s2[tid], s);
        atomicAdd(&g_q2[tid], q);
    }
}

// ---------------------------------------------------------------------------
// K4: BN2-finalize + e = max_k lrelu(bn2) + att = sigmoid(W_agg@e + b).
// Block per n, 256 threads.
// ---------------------------------------------------------------------------
__global__ void __launch_bounds__(256) k_att(const float* __restrict__ g2,
                                             const float* __restrict__ b2,
                                             const float* __restrict__ Wa,
                                             const float* __restrict__ ba) {
    int n = blockIdx.x;
    int tid = threadIdx.x;
    __shared__ float se[CI * L];      // [d][l]
    if (tid < CI) {
        int d = tid;
        float s = g_s2[d], q = g_q2[d];
        float cnt = (float)(NB * L * K);
        float mean = s / cnt;
        float rstd = rsqrtf(q / cnt - mean * mean + EPSV);
        float gm = __ldg(&g2[d]), bt = __ldg(&b2[d]);
#pragma unroll
        for (int l = 0; l < L; l++) {
            float mx = -INFINITY;
#pragma unroll
            for (int k = 0; k < K; k++) {
                float e = (__ldg(&g_epre[((n * CI + d) * L + l) * K + k]) - mean) * rstd * gm + bt;
                e = (e >= 0.f) ? e : 0.2f * e;
                mx = fmaxf(mx, e);
            }
            se[d * L + l] = mx;
        }
    }
    __syncthreads();
    float acc[L];
#pragma unroll
    for (int l = 0; l < L; l++) acc[l] = 0.f;
    const float4* Wa4 = (const float4*)(Wa + tid * CI);
#pragma unroll 4
    for (int j = 0; j < 16; j++) {
        float4 w = __ldg(Wa4 + j);
        int d0 = j * 4;
#pragma unroll
        for (int l = 0; l < L; l++) {
            acc[l] += w.x * se[(d0 + 0) * L + l] + w.y * se[(d0 + 1) * L + l]
                    + w.z * se[(d0 + 2) * L + l] + w.w * se[(d0 + 3) * L + l];
        }
    }
    float bb = __ldg(&ba[tid]);
#pragma unroll
    for (int l = 0; l < L; l++) {
        float a = acc[l] + bb;
        g_att[(n * C + tid) * L + l] = 1.f / (1.f + expf(-a));
    }
}

// ---------------------------------------------------------------------------
// K5: out[n,c,t,v] = sum_l x[n,c,l,t,v]*att[n,c,l], float4.
// ---------------------------------------------------------------------------
__global__ void __launch_bounds__(256) k_out(const float* __restrict__ x,
                                             float* __restrict__ out) {
    int i4 = blockIdx.x * 256 + threadIdx.x;           // over OUT_ELEMS/4
    if (i4 >= OUT_ELEMS / 4) return;
    int tv4 = i4 % (T * V / 4);                        // 0..799
    int nc  = i4 / (T * V / 4);
    const float4* px = (const float4*)x + (size_t)nc * (L * T * V / 4) + tv4;
    float a0 = __ldg(&g_att[nc * L + 0]);
    float a1 = __ldg(&g_att[nc * L + 1]);
    float a2 = __ldg(&g_att[nc * L + 2]);
    float a3 = __ldg(&g_att[nc * L + 3]);
    float a4 = __ldg(&g_att[nc * L + 4]);
    float a5 = __ldg(&g_att[nc * L + 5]);
    float4 x0 = __ldg(px + 0 * 800);
    float4 x1 = __ldg(px + 1 * 800);
    float4 x2 = __ldg(px + 2 * 800);
    float4 x3 = __ldg(px + 3 * 800);
    float4 x4 = __ldg(px + 4 * 800);
    float4 x5 = __ldg(px + 5 * 800);
    float4 r;
    r.x = a0*x0.x + a1*x1.x + a2*x2.x + a3*x3.x + a4*x4.x + a5*x5.x;
    r.y = a0*x0.y + a1*x1.y + a2*x2.y + a3*x3.y + a4*x4.y + a5*x5.y;
    r.z = a0*x0.z + a1*x1.z + a2*x2.z + a3*x3.z + a4*x4.z + a5*x5.z;
    r.w = a0*x0.w + a1*x1.w + a2*x2.w + a3*x3.w + a4*x4.w + a5*x5.w;
    ((float4*)out)[i4] = r;
}

// ---------------------------------------------------------------------------
extern "C" void kernel_launch(void* const* d_in, const int* in_sizes, int n_in,
                              void* d_out, int out_size) {
    const float* x      = (const float*)d_in[0];
    const float* W_down = (const float*)d_in[1];
    const float* b_down = (const float*)d_in[2];
    const float* gamma1 = (const float*)d_in[3];
    const float* beta1  = (const float*)d_in[4];
    const float* W_edge = (const float*)d_in[5];
    const float* gamma2 = (const float*)d_in[6];
    const float* beta2  = (const float*)d_in[7];
    const float* W_agg  = (const float*)d_in[8];
    const float* b_agg  = (const float*)d_in[9];
    float* out = (float*)d_out;

    k_maxT<<<(XT_ELEMS / 2 + 255) / 256, 256>>>(x, W_down);
    k_down<<<NB * L, 256>>>(b_down);
    k_graph<<<NB, 384>>>(gamma1, beta1, W_edge);
    k_att<<<NB, 256>>>(gamma2, beta2, W_agg, b_agg);
    k_out<<<(OUT_ELEMS / 4 + 255) / 256, 256>>>(x, out);
}

// round 4
// speedup vs baseline: 1.3258x; 1.0168x over previous
#include <cuda_runtime.h>
#include <math.h>

#define NB   32
#define C    256
#define CI   64
#define L    6
#define T    64
#define V    50
#define K    3
#define EPSV 1e-5f

#define XT_ELEMS  (NB*C*L*V)      // 2,457,600
#define Y_ELEMS   (NB*CI*L*V)     // 614,400
#define OUT_ELEMS (NB*C*T*V)      // 26,214,400

__device__ __align__(16) float g_xt[XT_ELEMS];
__device__ __align__(16) float g_WdT[C*CI];     // [c][d]
__device__ __align__(16) float g_y[Y_ELEMS];
__device__ __align__(16) float g_epre[NB*L*K*CI]; // [n][l][k][d]
__device__ float g_att[NB*C*L];
__device__ float g_s1[CI], g_q1[CI];
__device__ float g_s2[CI], g_q2[CI];

__constant__ int c_off[7] = {0, 6, 20, 42, 62, 78, 94};
__constant__ int c_layers[94] = {
    1, 0, 20, 26, 25, 45,
    0, 20, 12, 16, 2, 4, 8, 25, 45, 37, 41, 27, 29, 33,
    12, 16, 2, 4, 8, 13, 17, 3, 5, 9, 3, 28, 37, 41, 27, 29, 33, 38, 42, 28, 30, 34,
    13, 17, 3, 5, 9, 14, 18, 6, 10, 3, 28, 38, 42, 28, 30, 34, 39, 43, 31, 35,
    14, 18, 6, 10, 15, 19, 7, 11, 39, 43, 31, 35, 40, 44, 32, 36,
    15, 19, 7, 11, 21, 22, 23, 24, 40, 44, 32, 36, 46, 47, 48, 49
};

// ---------------------------------------------------------------------------
// K1: x_t = max over T (float2). Side jobs: transpose W_down, zero BN sums.
// ---------------------------------------------------------------------------
__global__ void __launch_bounds__(256) k_maxT(const float* __restrict__ x,
                                              const float* __restrict__ Wd) {
    if (blockIdx.x < 64) {
        g_WdT[threadIdx.x * CI + blockIdx.x] = Wd[blockIdx.x * C + threadIdx.x];
    } else if (blockIdx.x == 64 && threadIdx.x < CI) {
        int t = threadIdx.x;
        g_s1[t] = 0.f; g_q1[t] = 0.f; g_s2[t] = 0.f; g_q2[t] = 0.f;
    }
    int i2 = blockIdx.x * 256 + threadIdx.x;
    if (i2 >= XT_ELEMS / 2) return;
    int v2  = i2 % (V / 2);
    int ncl = i2 / (V / 2);
    const float2* p = (const float2*)x + (size_t)ncl * (T * V / 2) + v2;
    float ax0 = -INFINITY, ay0 = -INFINITY, ax1 = -INFINITY, ay1 = -INFINITY;
    float ax2 = -INFINITY, ay2 = -INFINITY, ax3 = -INFINITY, ay3 = -INFINITY;
#pragma unroll
    for (int t = 0; t < T; t += 4) {
        float2 q0 = __ldg(p + (t + 0) * (V / 2));
        float2 q1 = __ldg(p + (t + 1) * (V / 2));
        float2 q2 = __ldg(p + (t + 2) * (V / 2));
        float2 q3 = __ldg(p + (t + 3) * (V / 2));
        ax0 = fmaxf(ax0, q0.x); ay0 = fmaxf(ay0, q0.y);
        ax1 = fmaxf(ax1, q1.x); ay1 = fmaxf(ay1, q1.y);
        ax2 = fmaxf(ax2, q2.x); ay2 = fmaxf(ay2, q2.y);
        ax3 = fmaxf(ax3, q3.x); ay3 = fmaxf(ay3, q3.y);
    }
    float2 r;
    r.x = fmaxf(fmaxf(ax0, ax1), fmaxf(ax2, ax3));
    r.y = fmaxf(fmaxf(ay0, ay1), fmaxf(ay2, ay3));
    ((float2*)g_xt)[i2] = r;
}

// ---------------------------------------------------------------------------
// K2: y = W_down @ xt + b (smem-tiled), fused BN1 partial sums.
// Block per (n,l), 512 threads (400 active): v=tid%50, dg=tid/50 (0..7).
// ---------------------------------------------------------------------------
__global__ void __launch_bounds__(512) k_down(const float* __restrict__ bd) {
    int n = blockIdx.x / L;
    int l = blockIdx.x % L;
    __shared__ __align__(16) float sW[64 * 64];   // [c_local][d]
    __shared__ __align__(16) float sx[64 * V];
    int tid = threadIdx.x;
    int v = tid % V;
    int dg = tid / V;               // 0..7 active (tid<400)
    float acc[8];
#pragma unroll
    for (int i = 0; i < 8; i++) acc[i] = 0.f;

    for (int ch = 0; ch < 4; ch++) {
        int cb = ch * 64;
        const float4* Wg = (const float4*)(g_WdT + cb * CI);
        float4* sW4 = (float4*)sW;
        for (int j = tid; j < 1024; j += 512) sW4[j] = __ldg(Wg + j);
        for (int j = tid; j < 1600; j += 512) {
            int cl = j / 25, v2 = j % 25;
            ((float2*)sx)[cl * 25 + v2] =
                *(const float2*)(g_xt + (size_t)(n * C + cb + cl) * (L * V) + l * V + v2 * 2);
        }
        __syncthreads();
        if (tid < 400) {
#pragma unroll 8
            for (int cl = 0; cl < 64; cl++) {
                float xv = sx[cl * V + v];
                const float4* w4 = (const float4*)(sW + cl * 64 + dg * 8);
                float4 w0 = w4[0], w1 = w4[1];
                acc[0] += w0.x * xv; acc[1] += w0.y * xv; acc[2] += w0.z * xv; acc[3] += w0.w * xv;
                acc[4] += w1.x * xv; acc[5] += w1.y * xv; acc[6] += w1.z * xv; acc[7] += w1.w * xv;
            }
        }
        __syncthreads();
    }
    if (tid < 400) {
#pragma unroll
        for (int i = 0; i < 8; i++) {
            int d = dg * 8 + i;
            float yv = acc[i] + __ldg(&bd[d]);
            g_y[((n * CI + d) * L + l) * V + v] = yv;
            sx[d * V + v] = yv;
        }
    }
    __syncthreads();
    if (tid < CI) {
        float s = 0.f, q = 0.f;
#pragma unroll
        for (int vv = 0; vv < V; vv++) {
            float yv = sx[tid * V + vv];
            s += yv; q += yv * yv;
        }
        atomicAdd(&g_s1[tid], s);
        atomicAdd(&g_q1[tid], q);
    }
}

// ---------------------------------------------------------------------------
// K3: fused BN1-finalize + xs + topk graph + edge GEMM + BN2 partial sums.
// Block per n, 384 threads = (l*64 + d).
// ---------------------------------------------------------------------------
__global__ void __launch_bounds__(384) k_graph(const float* __restrict__ g1,
                                               const float* __restrict__ b1,
                                               const float* __restrict__ We) {
    int n = blockIdx.x;
    int tid = threadIdx.x;
    int d = tid & 63;
    int l = tid / 64;
    __shared__ float sWe[CI * 129];
    __shared__ float sxs[CI * L];
    __shared__ float sstat[2 * CI];
    __shared__ float sinn[L * L];
    __shared__ int   sidx[L * K];
    __shared__ float sred[L * CI], sredq[L * CI];

    const float4* We4 = (const float4*)We;
    for (int j = tid; j < 2048; j += 384) {
        float4 w = __ldg(We4 + j);
        int dd = j >> 5, c4 = (j & 31) * 4;
        float* p = &sWe[dd * 129 + c4];
        p[0] = w.x; p[1] = w.y; p[2] = w.z; p[3] = w.w;
    }
    if (tid < CI) {
        float s = g_s1[tid], q = g_q1[tid];
        float cnt = (float)(NB * L * V);
        float mean = s / cnt;
        float var  = q / cnt - mean * mean;
        sstat[tid]      = mean;
        sstat[CI + tid] = rsqrtf(var + EPSV);
    }
    __syncthreads();

    {
        float mean = sstat[d], rstd = sstat[CI + d];
        float gm = __ldg(&g1[d]), bt = __ldg(&b1[d]);
        int base = (n * CI + d) * (L * V) + l * V;
        int o0 = c_off[l], o1 = c_off[l + 1];
        float s = 0.f;
        for (int j = o0; j < o1; j++) {
            float yv = (__ldg(&g_y[base + c_layers[j]]) - mean) * rstd * gm + bt;
            s += fmaxf(yv, 0.f);
        }
        sxs[d * L + l] = s / (float)(o1 - o0);
    }
    __syncthreads();

    if (tid < L * L) {
        int ll = tid / L, mm = tid % L;
        float s = 0.f;
        for (int c = 0; c < CI; c++) s += sxs[c * L + ll] * sxs[c * L + mm];
        sinn[tid] = s;
    }
    __syncthreads();
    if (tid < L) {
        int taken = 0;
        float xl = sinn[tid * L + tid];
        for (int k = 0; k < K; k++) {
            int best = -1; float bv = -INFINITY;
            for (int m = 0; m < L; m++) {
                if ((taken >> m) & 1) continue;
                float pv = 2.f * sinn[tid * L + m] - xl - sinn[m * L + m];
                if (pv > bv) { bv = pv; best = m; }
            }
            taken |= (1 << best);
            sidx[tid * K + k] = best;
        }
    }
    __syncthreads();

    int i0 = sidx[l * K + 0], i1 = sidx[l * K + 1], i2 = sidx[l * K + 2];
    float a0 = 0.f, a1 = 0.f, a2 = 0.f;
#pragma unroll 4
    for (int c = 0; c < CI; c++) {
        float wa = sWe[d * 129 + c];
        float wb = sWe[d * 129 + CI + c];
        float ctr = sxs[c * L + l];
        float base = (wb - wa) * ctr;
        a0 += wa * sxs[c * L + i0] + base;
        a1 += wa * sxs[c * L + i1] + base;
        a2 += wa * sxs[c * L + i2] + base;
    }
    // epre layout [n][l][k][d] — d-coalesced
    int ob = (n * L + l) * K * CI + d;
    g_epre[ob + 0 * CI] = a0;
    g_epre[ob + 1 * CI] = a1;
    g_epre[ob + 2 * CI] = a2;
    sred [l * CI + d] = a0 + a1 + a2;
    sredq[l * CI + d] = a0 * a0 + a1 * a1 + a2 * a2;
    __syncthreads();
    if (tid < CI) {
        float s = 0.f, q = 0.f;
#pragma unroll
        for (int ll = 0; ll < L; ll++) {
            s += sred [ll * CI + tid];
            q += sredq[ll * CI + tid];
        }
        atomicAdd(&g_s2[tid], s);
        atomicAdd(&g_q2[tid], q);
    }
}

// ---------------------------------------------------------------------------
// K4: BN2-finalize + e = max_k lrelu(bn2) + att = sigmoid(W_agg@e + b).
// Block per n, 256 threads. se padded to [d][8] for vector smem loads.
// ---------------------------------------------------------------------------
__global__ void __launch_bounds__(256) k_att(const float* __restrict__ g2,
                                             const float* __restrict__ b2,
                                             const float* __restrict__ Wa,
                                             const float* __restrict__ ba) {
    int n = blockIdx.x;
    int tid = threadIdx.x;
    __shared__ __align__(16) float se[CI * 8];   // [d][l], padded
    __shared__ float sstat[2 * CI];
    if (tid < CI) {
        float s = g_s2[tid], q = g_q2[tid];
        float cnt = (float)(NB * L * K);
        float mean = s / cnt;
        sstat[tid]      = mean;
        sstat[CI + tid] = rsqrtf(q / cnt - mean * mean + EPSV);
    }
    __syncthreads();
    // 384 (d,l) entries over 256 threads, d-coalesced epre loads
#pragma unroll
    for (int e = tid; e < CI * L; e += 256) {
        int d = e & 63, l = e >> 6;
        float mean = sstat[d], rstd = sstat[CI + d];
        float gm = __ldg(&g2[d]), bt = __ldg(&b2[d]);
        int base = (n * L + l) * K * CI + d;
        float mx = -INFINITY;
#pragma unroll
        for (int k = 0; k < K; k++) {
            float ev = (__ldg(&g_epre[base + k * CI]) - mean) * rstd * gm + bt;
            ev = (ev >= 0.f) ? ev : 0.2f * ev;
            mx = fmaxf(mx, ev);
        }
        se[d * 8 + l] = mx;
    }
    __syncthreads();
    float acc[L];
#pragma unroll
    for (int l = 0; l < L; l++) acc[l] = 0.f;
    const float4* Wa4 = (const float4*)(Wa + tid * CI);
#pragma unroll 4
    for (int j = 0; j < 16; j++) {
        float4 w = __ldg(Wa4 + j);
        float wv[4] = {w.x, w.y, w.z, w.w};
#pragma unroll
        for (int i = 0; i < 4; i++) {
            int d = j * 4 + i;
            float4 lo = *(const float4*)&se[d * 8];
            float2 hi = *(const float2*)&se[d * 8 + 4];
            acc[0] += wv[i] * lo.x; acc[1] += wv[i] * lo.y;
            acc[2] += wv[i] * lo.z; acc[3] += wv[i] * lo.w;
            acc[4] += wv[i] * hi.x; acc[5] += wv[i] * hi.y;
        }
    }
    float bb = __ldg(&ba[tid]);
#pragma unroll
    for (int l = 0; l < L; l++) {
        float a = acc[l] + bb;
        g_att[(n * C + tid) * L + l] = 1.f / (1.f + expf(-a));
    }
}

// ---------------------------------------------------------------------------
// K5: out[n,c,t,v] = sum_l x[n,c,l,t,v]*att[n,c,l], float4.
// ---------------------------------------------------------------------------
__global__ void __launch_bounds__(256) k_out(const float* __restrict__ x,
                                             float* __restrict__ out) {
    int i4 = blockIdx.x * 256 + threadIdx.x;
    if (i4 >= OUT_ELEMS / 4) return;
    int tv4 = i4 % (T * V / 4);
    int nc  = i4 / (T * V / 4);
    const float4* px = (const float4*)x + (size_t)nc * (L * T * V / 4) + tv4;
    float a0 = __ldg(&g_att[nc * L + 0]);
    float a1 = __ldg(&g_att[nc * L + 1]);
    float a2 = __ldg(&g_att[nc * L + 2]);
    float a3 = __ldg(&g_att[nc * L + 3]);
    float a4 = __ldg(&g_att[nc * L + 4]);
    float a5 = __ldg(&g_att[nc * L + 5]);
    float4 x0 = __ldg(px + 0 * 800);
    float4 x1 = __ldg(px + 1 * 800);
    float4 x2 = __ldg(px + 2 * 800);
    float4 x3 = __ldg(px + 3 * 800);
    float4 x4 = __ldg(px + 4 * 800);
    float4 x5 = __ldg(px + 5 * 800);
    float4 r;
    r.x = a0*x0.x + a1*x1.x + a2*x2.x + a3*x3.x + a4*x4.x + a5*x5.x;
    r.y = a0*x0.y + a1*x1.y + a2*x2.y + a3*x3.y + a4*x4.y + a5*x5.y;
    r.z = a0*x0.z + a1*x1.z + a2*x2.z + a3*x3.z + a4*x4.z + a5*x5.z;
    r.w = a0*x0.w + a1*x1.w + a2*x2.w + a3*x3.w + a4*x4.w + a5*x5.w;
    ((float4*)out)[i4] = r;
}

// ---------------------------------------------------------------------------
extern "C" void kernel_launch(void* const* d_in, const int* in_sizes, int n_in,
                              void* d_out, int out_size) {
    const float* x      = (const float*)d_in[0];
    const float* W_down = (const float*)d_in[1];
    const float* b_down = (const float*)d_in[2];
    const float* gamma1 = (const float*)d_in[3];
    const float* beta1  = (const float*)d_in[4];
    const float* W_edge = (const float*)d_in[5];
    const float* gamma2 = (const float*)d_in[6];
    const float* beta2  = (const float*)d_in[7];
    const float* W_agg  = (const float*)d_in[8];
    const float* b_agg  = (const float*)d_in[9];
    float* out = (float*)d_out;

    k_maxT<<<(XT_ELEMS / 2 + 255) / 256, 256>>>(x, W_down);
    k_down<<<NB * L, 512>>>(b_down);
    k_graph<<<NB, 384>>>(gamma1, beta1, W_edge);
    k_att<<<NB, 256>>>(gamma2, beta2, W_agg, b_agg);
    k_out<<<(OUT_ELEMS / 4 + 255) / 256, 256>>>(x, out);
}

// round 5
// speedup vs baseline: 1.3369x; 1.0083x over previous
#include <cuda_runtime.h>
#include <math.h>

#define NB   32
#define C    256
#define CI   64
#define L    6
#define T    64
#define V    50
#define K    3
#define EPSV 1e-5f

#define XT_ELEMS  (NB*C*L*V)
#define Y_ELEMS   (NB*CI*L*V)
#define OUT_ELEMS (NB*C*T*V)

__device__ __align__(16) float g_xt[XT_ELEMS];
__device__ __align__(16) float g_WdT[C*CI];       // [c][d]
__device__ __align__(16) float g_y[Y_ELEMS];
__device__ __align__(16) float g_epre[NB*L*K*CI]; // [n][l][k][d]
__device__ float g_att[NB*C*L];
__device__ float g_s1[CI], g_q1[CI];
__device__ float g_s2[CI], g_q2[CI];

__constant__ int c_off[7] = {0, 6, 20, 42, 62, 78, 94};
__constant__ int c_layers[94] = {
    1, 0, 20, 26, 25, 45,
    0, 20, 12, 16, 2, 4, 8, 25, 45, 37, 41, 27, 29, 33,
    12, 16, 2, 4, 8, 13, 17, 3, 5, 9, 3, 28, 37, 41, 27, 29, 33, 38, 42, 28, 30, 34,
    13, 17, 3, 5, 9, 14, 18, 6, 10, 3, 28, 38, 42, 28, 30, 34, 39, 43, 31, 35,
    14, 18, 6, 10, 15, 19, 7, 11, 39, 43, 31, 35, 40, 44, 32, 36,
    15, 19, 7, 11, 21, 22, 23, 24, 40, 44, 32, 36, 46, 47, 48, 49
};

// ---------------------------------------------------------------------------
// K1: x_t = max over T (float2). Side jobs: transpose W_down, zero BN sums.
// ---------------------------------------------------------------------------
__global__ void __launch_bounds__(256) k_maxT(const float* __restrict__ x,
                                              const float* __restrict__ Wd) {
    if (blockIdx.x < 64) {
        g_WdT[threadIdx.x * CI + blockIdx.x] = Wd[blockIdx.x * C + threadIdx.x];
    } else if (blockIdx.x == 64 && threadIdx.x < CI) {
        int t = threadIdx.x;
        g_s1[t] = 0.f; g_q1[t] = 0.f; g_s2[t] = 0.f; g_q2[t] = 0.f;
    }
    int i2 = blockIdx.x * 256 + threadIdx.x;
    if (i2 >= XT_ELEMS / 2) return;
    int v2  = i2 % (V / 2);
    int ncl = i2 / (V / 2);
    const float2* p = (const float2*)x + (size_t)ncl * (T * V / 2) + v2;
    float ax0 = -INFINITY, ay0 = -INFINITY, ax1 = -INFINITY, ay1 = -INFINITY;
    float ax2 = -INFINITY, ay2 = -INFINITY, ax3 = -INFINITY, ay3 = -INFINITY;
#pragma unroll
    for (int t = 0; t < T; t += 4) {
        float2 q0 = __ldg(p + (t + 0) * (V / 2));
        float2 q1 = __ldg(p + (t + 1) * (V / 2));
        float2 q2 = __ldg(p + (t + 2) * (V / 2));
        float2 q3 = __ldg(p + (t + 3) * (V / 2));
        ax0 = fmaxf(ax0, q0.x); ay0 = fmaxf(ay0, q0.y);
        ax1 = fmaxf(ax1, q1.x); ay1 = fmaxf(ay1, q1.y);
        ax2 = fmaxf(ax2, q2.x); ay2 = fmaxf(ay2, q2.y);
        ax3 = fmaxf(ax3, q3.x); ay3 = fmaxf(ay3, q3.y);
    }
    float2 r;
    r.x = fmaxf(fmaxf(ax0, ax1), fmaxf(ax2, ax3));
    r.y = fmaxf(fmaxf(ay0, ay1), fmaxf(ay2, ay3));
    ((float2*)g_xt)[i2] = r;
}

// ---------------------------------------------------------------------------
// K2: y = W_down @ xt + b (smem-tiled, 128-c chunks), fused BN1 partials.
// Block per (n,l), 512 threads (400 active).
// ---------------------------------------------------------------------------
__global__ void __launch_bounds__(512) k_down(const float* __restrict__ bd) {
    int n = blockIdx.x / L;
    int l = blockIdx.x % L;
    __shared__ __align__(16) float sW[128 * 64];   // 32 KB
    __shared__ __align__(16) float sx[128 * V];    // 25.6 KB
    int tid = threadIdx.x;
    int v = tid % V;
    int dg = tid / V;               // 0..7 active
    float acc[8];
#pragma unroll
    for (int i = 0; i < 8; i++) acc[i] = 0.f;

    for (int ch = 0; ch < 2; ch++) {
        int cb = ch * 128;
        const float4* Wg = (const float4*)(g_WdT + cb * CI);
        float4* sW4 = (float4*)sW;
        for (int j = tid; j < 2048; j += 512) sW4[j] = __ldg(Wg + j);
        for (int j = tid; j < 3200; j += 512) {
            int cl = j / 25, v2 = j % 25;
            ((float2*)sx)[cl * 25 + v2] =
                *(const float2*)(g_xt + (size_t)(n * C + cb + cl) * (L * V) + l * V + v2 * 2);
        }
        __syncthreads();
        if (tid < 400) {
#pragma unroll 8
            for (int cl = 0; cl < 128; cl++) {
                float xv = sx[cl * V + v];
                const float4* w4 = (const float4*)(sW + cl * 64 + dg * 8);
                float4 w0 = w4[0], w1 = w4[1];
                acc[0] += w0.x * xv; acc[1] += w0.y * xv; acc[2] += w0.z * xv; acc[3] += w0.w * xv;
                acc[4] += w1.x * xv; acc[5] += w1.y * xv; acc[6] += w1.z * xv; acc[7] += w1.w * xv;
            }
        }
        __syncthreads();
    }
    if (tid < 400) {
#pragma unroll
        for (int i = 0; i < 8; i++) {
            int d = dg * 8 + i;
            float yv = acc[i] + __ldg(&bd[d]);
            g_y[((n * CI + d) * L + l) * V + v] = yv;
            sx[d * V + v] = yv;
        }
    }
    __syncthreads();
    if (tid < CI) {
        float s = 0.f, q = 0.f;
#pragma unroll
        for (int vv = 0; vv < V; vv++) {
            float yv = sx[tid * V + vv];
            s += yv; q += yv * yv;
        }
        atomicAdd(&g_s1[tid], s);
        atomicAdd(&g_q1[tid], q);
    }
}

// ---------------------------------------------------------------------------
// K3: fused BN1-finalize + xs + topk graph + edge GEMM + BN2 partials.
// Block per n, 384 threads = (l*64 + d).
// ---------------------------------------------------------------------------
__global__ void __launch_bounds__(384) k_graph(const float* __restrict__ g1,
                                               const float* __restrict__ b1,
                                               const float* __restrict__ We) {
    int n = blockIdx.x;
    int tid = threadIdx.x;
    int d = tid & 63;
    int l = tid / 64;
    __shared__ float sWe[CI * 129];
    __shared__ float sxs[CI * L];
    __shared__ float sstat[2 * CI];
    __shared__ float sinn[L * L];
    __shared__ int   sidx[L * K];
    __shared__ float sred[L * CI], sredq[L * CI];

    const float4* We4 = (const float4*)We;
    for (int j = tid; j < 2048; j += 384) {
        float4 w = __ldg(We4 + j);
        int dd = j >> 5, c4 = (j & 31) * 4;
        float* p = &sWe[dd * 129 + c4];
        p[0] = w.x; p[1] = w.y; p[2] = w.z; p[3] = w.w;
    }
    if (tid < CI) {
        float s = g_s1[tid], q = g_q1[tid];
        float cnt = (float)(NB * L * V);
        float mean = s / cnt;
        float var  = q / cnt - mean * mean;
        sstat[tid]      = mean;
        sstat[CI + tid] = rsqrtf(var + EPSV);
    }
    __syncthreads();

    {
        float mean = sstat[d], rstd = sstat[CI + d];
        float gm = __ldg(&g1[d]), bt = __ldg(&b1[d]);
        int base = (n * CI + d) * (L * V) + l * V;
        int o0 = c_off[l], o1 = c_off[l + 1];
        float s = 0.f;
        for (int j = o0; j < o1; j++) {
            float yv = (__ldg(&g_y[base + c_layers[j]]) - mean) * rstd * gm + bt;
            s += fmaxf(yv, 0.f);
        }
        sxs[d * L + l] = s / (float)(o1 - o0);
    }
    __syncthreads();

    if (tid < L * L) {
        int ll = tid / L, mm = tid % L;
        float s = 0.f;
        for (int c = 0; c < CI; c++) s += sxs[c * L + ll] * sxs[c * L + mm];
        sinn[tid] = s;
    }
    __syncthreads();
    if (tid < L) {
        int taken = 0;
        float xl = sinn[tid * L + tid];
        for (int k = 0; k < K; k++) {
            int best = -1; float bv = -INFINITY;
            for (int m = 0; m < L; m++) {
                if ((taken >> m) & 1) continue;
                float pv = 2.f * sinn[tid * L + m] - xl - sinn[m * L + m];
                if (pv > bv) { bv = pv; best = m; }
            }
            taken |= (1 << best);
            sidx[tid * K + k] = best;
        }
    }
    __syncthreads();

    int i0 = sidx[l * K + 0], i1 = sidx[l * K + 1], i2 = sidx[l * K + 2];
    float a0 = 0.f, a1 = 0.f, a2 = 0.f;
#pragma unroll 4
    for (int c = 0; c < CI; c++) {
        float wa = sWe[d * 129 + c];
        float wb = sWe[d * 129 + CI + c];
        float ctr = sxs[c * L + l];
        float base = (wb - wa) * ctr;
        a0 += wa * sxs[c * L + i0] + base;
        a1 += wa * sxs[c * L + i1] + base;
        a2 += wa * sxs[c * L + i2] + base;
    }
    int ob = (n * L + l) * K * CI + d;
    g_epre[ob + 0 * CI] = a0;
    g_epre[ob + 1 * CI] = a1;
    g_epre[ob + 2 * CI] = a2;
    sred [l * CI + d] = a0 + a1 + a2;
    sredq[l * CI + d] = a0 * a0 + a1 * a1 + a2 * a2;
    __syncthreads();
    if (tid < CI) {
        float s = 0.f, q = 0.f;
#pragma unroll
        for (int ll = 0; ll < L; ll++) {
            s += sred [ll * CI + tid];
            q += sredq[ll * CI + tid];
        }
        atomicAdd(&g_s2[tid], s);
        atomicAdd(&g_q2[tid], q);
    }
}

// ---------------------------------------------------------------------------
// K4: BN2-finalize + e = max_k lrelu(bn2) + att = sigmoid(W_agg@e + b).
// Block per (n,l): 192 blocks, 256 threads (thread = output channel c).
// ---------------------------------------------------------------------------
__global__ void __launch_bounds__(256) k_att(const float* __restrict__ g2,
                                             const float* __restrict__ b2,
                                             const float* __restrict__ Wa,
                                             const float* __restrict__ ba) {
    int n = blockIdx.x / L;
    int l = blockIdx.x % L;
    int tid = threadIdx.x;
    __shared__ __align__(16) float se[CI];    // e[d] for this (n,l)
    if (tid < CI) {
        int d = tid;
        float s = g_s2[d], q = g_q2[d];
        float cnt = (float)(NB * L * K);
        float mean = s / cnt;
        float rstd = rsqrtf(q / cnt - mean * mean + EPSV);
        float gm = __ldg(&g2[d]), bt = __ldg(&b2[d]);
        int base = (n * L + l) * K * CI + d;
        float e0 = __ldg(&g_epre[base + 0 * CI]);
        float e1 = __ldg(&g_epre[base + 1 * CI]);
        float e2 = __ldg(&g_epre[base + 2 * CI]);
        float mx = -INFINITY;
        float ev;
        ev = (e0 - mean) * rstd * gm + bt; ev = (ev >= 0.f) ? ev : 0.2f * ev; mx = fmaxf(mx, ev);
        ev = (e1 - mean) * rstd * gm + bt; ev = (ev >= 0.f) ? ev : 0.2f * ev; mx = fmaxf(mx, ev);
        ev = (e2 - mean) * rstd * gm + bt; ev = (ev >= 0.f) ? ev : 0.2f * ev; mx = fmaxf(mx, ev);
        se[d] = mx;
    }
    __syncthreads();
    float acc = 0.f;
    const float4* Wa4 = (const float4*)(Wa + tid * CI);
    const float4* se4 = (const float4*)se;
#pragma unroll
    for (int j = 0; j < 16; j++) {
        float4 w = __ldg(Wa4 + j);
        float4 e = se4[j];
        acc += w.x * e.x + w.y * e.y + w.z * e.z + w.w * e.w;
    }
    float a = acc + __ldg(&ba[tid]);
    g_att[(n * C + tid) * L + l] = 1.f / (1.f + __expf(-a));
}

// ---------------------------------------------------------------------------
// K5: out[n,c,t,v] = sum_l x[n,c,l,t,v]*att[n,c,l], float4.
// ---------------------------------------------------------------------------
__global__ void __launch_bounds__(256) k_out(const float* __restrict__ x,
                                             float* __restrict__ out) {
    int i4 = blockIdx.x * 256 + threadIdx.x;
    if (i4 >= OUT_ELEMS / 4) return;
    int tv4 = i4 % (T * V / 4);
    int nc  = i4 / (T * V / 4);
    const float4* px = (const float4*)x + (size_t)nc * (L * T * V / 4) + tv4;
    float a0 = __ldg(&g_att[nc * L + 0]);
    float a1 = __ldg(&g_att[nc * L + 1]);
    float a2 = __ldg(&g_att[nc * L + 2]);
    float a3 = __ldg(&g_att[nc * L + 3]);
    float a4 = __ldg(&g_att[nc * L + 4]);
    float a5 = __ldg(&g_att[nc * L + 5]);
    float4 x0 = __ldg(px + 0 * 800);
    float4 x1 = __ldg(px + 1 * 800);
    float4 x2 = __ldg(px + 2 * 800);
    float4 x3 = __ldg(px + 3 * 800);
    float4 x4 = __ldg(px + 4 * 800);
    float4 x5 = __ldg(px + 5 * 800);
    float4 r;
    r.x = a0*x0.x + a1*x1.x + a2*x2.x + a3*x3.x + a4*x4.x + a5*x5.x;
    r.y = a0*x0.y + a1*x1.y + a2*x2.y + a3*x3.y + a4*x4.y + a5*x5.y;
    r.z = a0*x0.z + a1*x1.z + a2*x2.z + a3*x3.z + a4*x4.z + a5*x5.z;
    r.w = a0*x0.w + a1*x1.w + a2*x2.w + a3*x3.w + a4*x4.w + a5*x5.w;
    ((float4*)out)[i4] = r;
}

// ---------------------------------------------------------------------------
extern "C" void kernel_launch(void* const* d_in, const int* in_sizes, int n_in,
                              void* d_out, int out_size) {
    const float* x      = (const float*)d_in[0];
    const float* W_down = (const float*)d_in[1];
    const float* b_down = (const float*)d_in[2];
    const float* gamma1 = (const float*)d_in[3];
    const float* beta1  = (const float*)d_in[4];
    const float* W_edge = (const float*)d_in[5];
    const float* gamma2 = (const float*)d_in[6];
    const float* beta2  = (const float*)d_in[7];
    const float* W_agg  = (const float*)d_in[8];
    const float* b_agg  = (const float*)d_in[9];
    float* out = (float*)d_out;

    k_maxT<<<(XT_ELEMS / 2 + 255) / 256, 256>>>(x, W_down);
    k_down<<<NB * L, 512>>>(b_down);
    k_graph<<<NB, 384>>>(gamma1, beta1, W_edge);
    k_att<<<NB * L, 256>>>(gamma2, beta2, W_agg, b_agg);
    k_out<<<(OUT_ELEMS / 4 + 255) / 256, 256>>>(x, out);
}